// round 15
// baseline (speedup 1.0000x reference)
#include <cuda_runtime.h>
#include <cuda_fp16.h>
#include <math.h>

#define B_  16
#define T_  2048
#define C_  768
#define H_  64
#define BT_ (B_*T_)

// Scratch (allocation-free rule: device globals) — all fp16-rounded
__device__ __half g_Qh[BT_*H_];
__device__ __half g_Kh[BT_*H_];
__device__ __half g_Vh[BT_*H_];

// ---------------------------------------------------------------------------
// helpers
// ---------------------------------------------------------------------------
__device__ __forceinline__ unsigned smem_u32(const void* p) {
    unsigned a;
    asm("{ .reg .u64 t; cvta.to.shared.u64 t, %1; cvt.u32.u64 %0, t; }"
        : "=r"(a) : "l"(p));
    return a;
}
__device__ __forceinline__ void ldsm4(unsigned* r, unsigned addr) {
    asm volatile("ldmatrix.sync.aligned.m8n8.x4.shared.b16 {%0,%1,%2,%3}, [%4];"
                 : "=r"(r[0]), "=r"(r[1]), "=r"(r[2]), "=r"(r[3]) : "r"(addr));
}
__device__ __forceinline__ void ldsm4_t(unsigned* r, unsigned addr) {
    asm volatile("ldmatrix.sync.aligned.m8n8.x4.trans.shared.b16 {%0,%1,%2,%3}, [%4];"
                 : "=r"(r[0]), "=r"(r[1]), "=r"(r[2]), "=r"(r[3]) : "r"(addr));
}
__device__ __forceinline__ void mma_f16(float* c, const unsigned* a, const unsigned* b) {
    asm volatile(
        "mma.sync.aligned.m16n8k16.row.col.f32.f16.f16.f32 "
        "{%0,%1,%2,%3}, {%4,%5,%6,%7}, {%8,%9}, {%0,%1,%2,%3};"
        : "+f"(c[0]), "+f"(c[1]), "+f"(c[2]), "+f"(c[3])
        : "r"(a[0]), "r"(a[1]), "r"(a[2]), "r"(a[3]), "r"(b[0]), "r"(b[1]));
}
__device__ __forceinline__ void cp_async16(unsigned dst, const void* src) {
    asm volatile("cp.async.cg.shared.global [%0], [%1], 16;"
                 :: "r"(dst), "l"(src) : "memory");
}
__device__ __forceinline__ void cp_commit() {
    asm volatile("cp.async.commit_group;" ::: "memory");
}
template<int N> __device__ __forceinline__ void cp_wait() {
    asm volatile("cp.async.wait_group %0;" :: "n"(N) : "memory");
}
// packed fp16x2 exp2
__device__ __forceinline__ unsigned h2exp2(unsigned d) {
    unsigned r;
    asm("ex2.approx.f16x2 %0, %1;" : "=r"(r) : "r"(d));
    return r;
}

union F2U { float2 f; unsigned long long u; };
__device__ __forceinline__ float2 ffma2(float2 a, float2 b, float2 c) {
    F2U A, Bv, C, D;
    A.f = a; Bv.f = b; C.f = c;
    asm("fma.rn.f32x2 %0, %1, %2, %3;"
        : "=l"(D.u) : "l"(A.u), "l"(Bv.u), "l"(C.u));
    return D.f;
}
__device__ __forceinline__ float2 dup2(float a) { return make_float2(a, a); }

// pack two fp32 into f16x2 (plain round)
__device__ __forceinline__ unsigned round2(float x, float y) {
    __half2 h2 = __halves2half2(__float2half_rn(x), __float2half_rn(y));
    return *reinterpret_cast<unsigned*>(&h2);
}
// pack 8 fp32 -> uint4 fp16
__device__ __forceinline__ uint4 round8(const float4& a, const float4& b) {
    uint4 o;
    o.x = round2(a.x, a.y);
    o.y = round2(a.z, a.w);
    o.z = round2(b.x, b.y);
    o.w = round2(b.z, b.w);
    return o;
}

// ============================================================================
// QKV GEMM on mma.sync fp16, 1-pass (unchanged from R14).
// ============================================================================
#define QK_STAGES 12
#define SA(b) ((b)*24576)
#define SB(b) ((b)*24576 + 16384)
#define QM_SMEM 49152

__global__ __launch_bounds__(256, 2)
void qkv_mma_kernel(const float* __restrict__ x, const float* __restrict__ v1,
                    const float* __restrict__ Wk, const float* __restrict__ Wq,
                    const float* __restrict__ Wv,
                    const float* __restrict__ lamb_p,
                    float* __restrict__ v1dst)
{
    extern __shared__ char smem[];
    const unsigned sb = smem_u32(smem);
    const int tid  = threadIdx.x;
    const int warp = tid >> 5;
    const int lane = tid & 31;
    const int wm   = warp & 3;
    const int wn   = warp >> 2;
    const int mat  = blockIdx.x;       // 0:K 1:Q 2:V
    const int row0 = blockIdx.y * 128;
    const float* __restrict__ W = (mat == 0) ? Wk : (mat == 1) ? Wq : Wv;

    float4 pa[4][2];
    float4 pw[4];
    const int arow = tid >> 3;
    const int ac8  = tid & 7;

    auto load_a = [&](int k0) {
        #pragma unroll
        for (int it = 0; it < 4; it++) {
            int row = arow + it * 32;
            const float* p = &x[(size_t)(row0 + row) * C_ + k0 + ac8 * 8];
            pa[it][0] = *reinterpret_cast<const float4*>(p);
            pa[it][1] = *reinterpret_cast<const float4*>(p + 4);
        }
    };
    auto load_w = [&](int k0) {
        #pragma unroll
        for (int it = 0; it < 4; it++) {
            int idx = tid + it * 256;
            int k   = idx >> 4;
            int c4  = idx & 15;
            pw[it] = *reinterpret_cast<const float4*>(
                &W[(size_t)(k0 + k) * H_ + c4 * 4]);
        }
    };
    auto store_ab = [&](int buf) {
        #pragma unroll
        for (int it = 0; it < 4; it++) {
            int row = arow + it * 32;
            unsigned boff = row * 128 + ((ac8 * 16) ^ ((row & 7) << 4));
            *reinterpret_cast<uint4*>(smem + SA(buf) + boff) =
                round8(pa[it][0], pa[it][1]);
        }
        #pragma unroll
        for (int it = 0; it < 4; it++) {
            int idx = tid + it * 256;
            int k   = idx >> 4;
            int c4  = idx & 15;
            uint2 h;
            h.x = round2(pw[it].x, pw[it].y);
            h.y = round2(pw[it].z, pw[it].w);
            unsigned boff = k * 128 + ((c4 * 8) ^ ((k & 7) << 4));
            *reinterpret_cast<uint2*>(smem + SB(buf) + boff) = h;
        }
    };

    const int r   = lane & 7;
    const int sel = lane >> 3;
    const unsigned rx = r << 4;
    unsigned rowA[2], kselA = (sel >> 1) * 16;
    #pragma unroll
    for (int mt = 0; mt < 2; mt++)
        rowA[mt] = (wm * 32 + mt * 16 + r + (sel & 1) * 8) * 128;
    unsigned offT[2];
    #pragma unroll
    for (int v = 0; v < 2; v++)
        offT[v] = (((2 * (wn * 2 + v) + (sel >> 1)) * 16) ^ rx);
    const int rbT_lane = (sel & 1) * 8 + r;

    float acc[2][4][4];
    #pragma unroll
    for (int mt = 0; mt < 2; mt++)
        #pragma unroll
        for (int nt = 0; nt < 4; nt++)
            #pragma unroll
            for (int e = 0; e < 4; e++) acc[mt][nt][e] = 0.0f;

    load_a(0);
    load_w(0);
    store_ab(0);
    __syncthreads();

    for (int t = 0; t < QK_STAGES; t++) {
        const int cur = t & 1;
        if (t + 1 < QK_STAGES) {
            load_a((t + 1) * 64);
            load_w((t + 1) * 64);
        }

        const unsigned sa = sb + SA(cur);
        const unsigned sbh = sb + SB(cur);

        #pragma unroll
        for (int ks = 0; ks < 4; ks++) {
            const unsigned kb = ks * 32;
            unsigned aH[2][4], bT[2][4];
            #pragma unroll
            for (int mt = 0; mt < 2; mt++) {
                unsigned off = ((kb + kselA) ^ rx);
                ldsm4(aH[mt], sa + rowA[mt] + off);
            }
            {
                unsigned rb = (ks * 16 + rbT_lane) * 128;
                ldsm4_t(bT[0], sbh + rb + offT[0]);
                ldsm4_t(bT[1], sbh + rb + offT[1]);
            }
            #pragma unroll
            for (int mt = 0; mt < 2; mt++)
                #pragma unroll
                for (int nt = 0; nt < 4; nt++)
                    mma_f16(acc[mt][nt], aH[mt], &bT[nt >> 1][(nt & 1) * 2]);
        }
        if (t + 1 < QK_STAGES) store_ab((t + 1) & 1);
        __syncthreads();
    }

    const float lam = *lamb_p;
    const int qr = lane >> 2;
    const int qc = (lane & 3) * 2;
    #pragma unroll
    for (int mt = 0; mt < 2; mt++)
        #pragma unroll
        for (int nt = 0; nt < 4; nt++)
            #pragma unroll
            for (int half = 0; half < 2; half++) {
                int row = row0 + wm * 32 + mt * 16 + qr + half * 8;
                int col = wn * 32 + nt * 8 + qc;
                float vx = acc[mt][nt][half * 2];
                float vy = acc[mt][nt][half * 2 + 1];
                size_t off = (size_t)row * H_ + col;
                if (mat == 0) {
                    *reinterpret_cast<unsigned*>(&g_Kh[off]) = round2(vx, vy);
                } else if (mat == 1) {
                    *reinterpret_cast<unsigned*>(&g_Qh[off]) = round2(vx, vy);
                } else {
                    float2 vv = *reinterpret_cast<const float2*>(&v1[off]);
                    if (v1dst != nullptr)
                        *reinterpret_cast<float2*>(&v1dst[off]) = vv;
                    vx = (1.0f - lam) * vx + lam * vv.x;
                    vy = (1.0f - lam) * vy + lam * vv.y;
                    *reinterpret_cast<unsigned*>(&g_Vh[off]) = round2(vx, vy);
                }
            }
}

// ============================================================================
// Tensor-core flash attention — register diet + occupancy 2.
// 64-key blocks processed as two 32-key halves (sacc 16 regs, pf 8 regs);
// Q fragments reloaded from resident smem per use (no persistent qh).
// ============================================================================
#define AT_QO   34816
#define AT_KV(b) (AT_QO + (b)*16384)
#define AT_SMEM (AT_QO + 2*16384)
#define OTS 132

__global__ __launch_bounds__(256, 2)
void attn_tc_kernel(const float* __restrict__ Wproj,
                    const float* __restrict__ bproj,
                    float* __restrict__ out)
{
    extern __shared__ char smem[];
    const unsigned sb = smem_u32(smem);
    const int bid  = blockIdx.x;
    const int b    = bid & 15;
    const int qt   = 15 - (bid >> 4);        // heavy tiles first
    const int tid  = threadIdx.x;
    const int warp = tid >> 5;
    const int lane = tid & 31;
    const int r    = lane & 7;
    const int sel  = lane >> 3;
    const unsigned rx = r << 4;
    const int q0   = qt * 128;
    const int rowbase = b * T_;
    const int nkb  = 2 * qt + 2;

    unsigned b_ones[2];
    b_ones[0] = b_ones[1] = ((lane >> 2) == 0) ? 0x3C003C00u : 0u;

    auto issue_kv = [&](int kb, int buf) {
        const __half* srcs[2] = {g_Kh, g_Vh};
        const unsigned dbase = sb + AT_KV(buf);
        #pragma unroll
        for (int it = 0; it < 4; it++) {
            int idx = tid + it * 256;
            int arr = idx >> 9;
            int row = (idx >> 3) & 63;
            int c   = idx & 7;
            const void* src = &srcs[arr][(size_t)(rowbase + kb * 64 + row) * H_ + c * 8];
            unsigned dst = dbase + arr * 8192 + row * 128 + ((c * 16) ^ ((row & 7) << 4));
            cp_async16(dst, src);
        }
        cp_commit();
    };

    issue_kv(0, 0);

    #pragma unroll
    for (int it = 0; it < 4; it++) {
        int idx = tid + it * 256;
        int row = (idx >> 3) & 127;
        int c   = idx & 7;
        uint4 v = *reinterpret_cast<const uint4*>(
            &g_Qh[(size_t)(rowbase + q0 + row) * H_ + c * 8]);
        *reinterpret_cast<uint4*>(
            smem + row * 128 + ((c * 16) ^ ((row & 7) << 4))) = v;
    }
    cp_wait<0>();
    __syncthreads();

    // Q fragment address base (reloaded per use — Q smem stays resident)
    const unsigned rbQ = (warp * 16 + r + (sel & 1) * 8) * 128;
    const unsigned kselQ = (sel >> 1) * 16;

    float oacc[8][4];
    float lacc[4];
    #pragma unroll
    for (int j = 0; j < 8; j++)
        #pragma unroll
        for (int e = 0; e < 4; e++) oacc[j][e] = 0.0f;
    #pragma unroll
    for (int e = 0; e < 4; e++) lacc[e] = 0.0f;
    float mi[2] = {-1e30f, -1e30f};

    const float alpha = 0.18033688f;   // 0.125 * log2(e)
    const int rk = r + ((sel & 2) ? 8 : 0);

    for (int kb = 0; kb < nkb; kb++) {
        const unsigned kvb = sb + AT_KV(kb & 1);
        cp_wait<0>();
        __syncthreads();
        if (kb + 1 < nkb) issue_kv(kb + 1, (kb + 1) & 1);

        const bool diag = (kb * 64 + 63 > q0 + warp * 16);

        #pragma unroll
        for (int g = 0; g < 2; g++) {      // 32-key halves
            // ---- S half: keys g*32 .. g*32+31 ----
            float sacc[4][4];
            #pragma unroll
            for (int j = 0; j < 4; j++)
                #pragma unroll
                for (int e = 0; e < 4; e++) sacc[j][e] = 0.0f;

            #pragma unroll
            for (int ks = 0; ks < 4; ks++) {
                unsigned qf[4];
                ldsm4(qf, sb + rbQ + ((ks * 32 + kselQ) ^ rx));
                const unsigned koff = ((ks * 32 + (sel & 1) * 16) ^ rx);
                unsigned kh[2][4];
                #pragma unroll
                for (int u2 = 0; u2 < 2; u2++) {
                    int u = g * 2 + u2;
                    ldsm4(kh[u2], kvb + (u * 16 + rk) * 128 + koff);
                }
                #pragma unroll
                for (int u2 = 0; u2 < 2; u2++)
                    #pragma unroll
                    for (int nn = 0; nn < 2; nn++)
                        mma_f16(sacc[u2 * 2 + nn], qf, &kh[u2][nn * 2]);
            }

            // ---- scale + causal mask ----
            if (diag) {
                #pragma unroll
                for (int j = 0; j < 4; j++)
                    #pragma unroll
                    for (int e = 0; e < 4; e++) {
                        int key  = kb * 64 + g * 32 + (j >> 1) * 16 + (j & 1) * 8
                                 + (lane & 3) * 2 + (e & 1);
                        int qrow = q0 + warp * 16 + (lane >> 2) + (e >> 1) * 8;
                        float v = sacc[j][e] * alpha;
                        sacc[j][e] = (key <= qrow) ? v : -1e30f;
                    }
            } else {
                #pragma unroll
                for (int j = 0; j < 4; j++)
                    #pragma unroll
                    for (int e = 0; e < 4; e++) sacc[j][e] *= alpha;
            }

            // ---- online softmax (per row-half) -> P fragments ----
            unsigned pf[2][4];
            #pragma unroll
            for (int h = 0; h < 2; h++) {
                float mx = -1e30f;
                #pragma unroll
                for (int j = 0; j < 4; j++)
                    mx = fmaxf(mx, fmaxf(sacc[j][h*2], sacc[j][h*2+1]));
                mx = fmaxf(mx, __shfl_xor_sync(0xffffffffu, mx, 1));
                mx = fmaxf(mx, __shfl_xor_sync(0xffffffffu, mx, 2));
                float mnew = fmaxf(mi[h], mx);
                float corr = exp2f(mi[h] - mnew);
                mi[h] = mnew;
                #pragma unroll
                for (int j = 0; j < 4; j++) {
                    __half2 d2 = __floats2half2_rn(sacc[j][h*2]   - mnew,
                                                   sacc[j][h*2+1] - mnew);
                    pf[j >> 1][(j & 1) * 2 + h] =
                        h2exp2(*reinterpret_cast<unsigned*>(&d2));
                }
                #pragma unroll
                for (int j = 0; j < 8; j++) {
                    oacc[j][h*2]   *= corr;
                    oacc[j][h*2+1] *= corr;
                }
                lacc[h*2]   *= corr;
                lacc[h*2+1] *= corr;
            }

            // ---- O += P V for this key half ----
            #pragma unroll
            for (int kt2 = 0; kt2 < 2; kt2++) {
                int kt = g * 2 + kt2;
                unsigned vh[4][4];
                const unsigned rb = (kt * 16 + (sel & 1) * 8 + r) * 128;
                #pragma unroll
                for (int u = 0; u < 4; u++) {
                    unsigned off = (((2 * u + (sel >> 1)) * 16) ^ rx);
                    ldsm4_t(vh[u], kvb + 8192 + rb + off);
                }
                #pragma unroll
                for (int u = 0; u < 4; u++)
                    #pragma unroll
                    for (int nn = 0; nn < 2; nn++)
                        mma_f16(oacc[u * 2 + nn], pf[kt2], &vh[u][nn * 2]);
                mma_f16(lacc, pf[kt2], b_ones);
            }
        }
    }

    // ---- epilogue ----
    __syncthreads();
    float li0 = __shfl_sync(0xffffffffu, lacc[0], lane & 28);
    float li1 = __shfl_sync(0xffffffffu, lacc[2], lane & 28);
    float* Ot = reinterpret_cast<float*>(smem);
    {
        float inv0 = 1.0f / li0, inv1 = 1.0f / li1;
        #pragma unroll
        for (int j = 0; j < 8; j++)
            #pragma unroll
            for (int e = 0; e < 4; e++) {
                int qrel = warp * 16 + (lane >> 2) + (e >> 1) * 8;
                int d    = j * 8 + (lane & 3) * 2 + (e & 1);
                Ot[d * OTS + qrel] = oacc[j][e] * ((e >> 1) ? inv1 : inv0);
            }
    }
    __syncthreads();

    const int tx = tid & 15;
    const int ty = tid >> 4;
    float2 r2[8][2];
    #pragma unroll
    for (int i = 0; i < 8; i++) {
        r2[i][0] = make_float2(0.f, 0.f);
        r2[i][1] = make_float2(0.f, 0.f);
    }
    #pragma unroll 4
    for (int d = 0; d < 64; d++) {
        float4 a0 = *reinterpret_cast<const float4*>(&Ot[d * OTS + ty * 8]);
        float4 a1 = *reinterpret_cast<const float4*>(&Ot[d * OTS + ty * 8 + 4]);
        float4 w  = *reinterpret_cast<const float4*>(&Wproj[d * 64 + tx * 4]);
        float2 w01 = make_float2(w.x, w.y);
        float2 w23 = make_float2(w.z, w.w);
        float a[8] = {a0.x, a0.y, a0.z, a0.w, a1.x, a1.y, a1.z, a1.w};
        #pragma unroll
        for (int i = 0; i < 8; i++) {
            float2 ad = dup2(a[i]);
            r2[i][0] = ffma2(ad, w01, r2[i][0]);
            r2[i][1] = ffma2(ad, w23, r2[i][1]);
        }
    }
    float4 bb = *reinterpret_cast<const float4*>(&bproj[tx * 4]);
    const size_t baseo = (size_t)b * T_ * H_;
    #pragma unroll
    for (int i = 0; i < 8; i++) {
        float4 ov = make_float4(r2[i][0].x + bb.x, r2[i][0].y + bb.y,
                                r2[i][1].x + bb.z, r2[i][1].y + bb.w);
        *reinterpret_cast<float4*>(
            &out[baseo + (size_t)(q0 + ty * 8 + i) * H_ + tx * 4]) = ov;
    }
}

extern "C" void kernel_launch(void* const* d_in, const int* in_sizes, int n_in,
                              void* d_out, int out_size)
{
    const float* x     = (const float*)d_in[0];
    const float* v1    = (const float*)d_in[1];
    const float* Wk    = (const float*)d_in[2];
    const float* Wq    = (const float*)d_in[3];
    const float* Wv    = (const float*)d_in[4];
    const float* Wproj = (const float*)d_in[5];
    const float* bproj = (const float*)d_in[6];
    const float* lamb  = (const float*)d_in[7];
    float* out = (float*)d_out;

    cudaFuncSetAttribute(qkv_mma_kernel,
                         cudaFuncAttributeMaxDynamicSharedMemorySize, QM_SMEM);
    cudaFuncSetAttribute(attn_tc_kernel,
                         cudaFuncAttributeMaxDynamicSharedMemorySize, AT_SMEM);

    float* v1dst = (out_size >= 2 * BT_ * H_) ? (out + (size_t)BT_ * H_) : nullptr;
    qkv_mma_kernel<<<dim3(3, BT_ / 128), 256, QM_SMEM>>>(x, v1, Wk, Wq, Wv,
                                                         lamb, v1dst);
    attn_tc_kernel<<<16 * B_, 256, AT_SMEM>>>(Wproj, bproj, out);
}

// round 16
// speedup vs baseline: 1.0929x; 1.0929x over previous
#include <cuda_runtime.h>
#include <cuda_fp16.h>
#include <math.h>

#define B_  16
#define T_  2048
#define C_  768
#define H_  64
#define BT_ (B_*T_)

// Scratch (allocation-free rule: device globals) — all fp16-rounded
__device__ __half g_Qh[BT_*H_];
__device__ __half g_Kh[BT_*H_];
__device__ __half g_Vh[BT_*H_];

// ---------------------------------------------------------------------------
// helpers
// ---------------------------------------------------------------------------
__device__ __forceinline__ unsigned smem_u32(const void* p) {
    unsigned a;
    asm("{ .reg .u64 t; cvta.to.shared.u64 t, %1; cvt.u32.u64 %0, t; }"
        : "=r"(a) : "l"(p));
    return a;
}
__device__ __forceinline__ void ldsm4(unsigned* r, unsigned addr) {
    asm volatile("ldmatrix.sync.aligned.m8n8.x4.shared.b16 {%0,%1,%2,%3}, [%4];"
                 : "=r"(r[0]), "=r"(r[1]), "=r"(r[2]), "=r"(r[3]) : "r"(addr));
}
__device__ __forceinline__ void ldsm4_t(unsigned* r, unsigned addr) {
    asm volatile("ldmatrix.sync.aligned.m8n8.x4.trans.shared.b16 {%0,%1,%2,%3}, [%4];"
                 : "=r"(r[0]), "=r"(r[1]), "=r"(r[2]), "=r"(r[3]) : "r"(addr));
}
__device__ __forceinline__ void mma_f16(float* c, const unsigned* a, const unsigned* b) {
    asm volatile(
        "mma.sync.aligned.m16n8k16.row.col.f32.f16.f16.f32 "
        "{%0,%1,%2,%3}, {%4,%5,%6,%7}, {%8,%9}, {%0,%1,%2,%3};"
        : "+f"(c[0]), "+f"(c[1]), "+f"(c[2]), "+f"(c[3])
        : "r"(a[0]), "r"(a[1]), "r"(a[2]), "r"(a[3]), "r"(b[0]), "r"(b[1]));
}
__device__ __forceinline__ void cp_async16(unsigned dst, const void* src) {
    asm volatile("cp.async.cg.shared.global [%0], [%1], 16;"
                 :: "r"(dst), "l"(src) : "memory");
}
__device__ __forceinline__ void cp_commit() {
    asm volatile("cp.async.commit_group;" ::: "memory");
}
template<int N> __device__ __forceinline__ void cp_wait() {
    asm volatile("cp.async.wait_group %0;" :: "n"(N) : "memory");
}
// packed fp16x2 exp2
__device__ __forceinline__ unsigned h2exp2(unsigned d) {
    unsigned r;
    asm("ex2.approx.f16x2 %0, %1;" : "=r"(r) : "r"(d));
    return r;
}

union F2U { float2 f; unsigned long long u; };
__device__ __forceinline__ float2 ffma2(float2 a, float2 b, float2 c) {
    F2U A, Bv, C, D;
    A.f = a; Bv.f = b; C.f = c;
    asm("fma.rn.f32x2 %0, %1, %2, %3;"
        : "=l"(D.u) : "l"(A.u), "l"(Bv.u), "l"(C.u));
    return D.f;
}
__device__ __forceinline__ float2 dup2(float a) { return make_float2(a, a); }

// pack two fp32 into f16x2 (plain round)
__device__ __forceinline__ unsigned round2(float x, float y) {
    __half2 h2 = __halves2half2(__float2half_rn(x), __float2half_rn(y));
    return *reinterpret_cast<unsigned*>(&h2);
}
// pack 8 fp32 -> uint4 fp16
__device__ __forceinline__ uint4 round8(const float4& a, const float4& b) {
    uint4 o;
    o.x = round2(a.x, a.y);
    o.y = round2(a.z, a.w);
    o.z = round2(b.x, b.y);
    o.w = round2(b.z, b.w);
    return o;
}

// ============================================================================
// QKV GEMM on mma.sync fp16, 1-pass (unchanged from R14).
// ============================================================================
#define QK_STAGES 12
#define SA(b) ((b)*24576)
#define SB(b) ((b)*24576 + 16384)
#define QM_SMEM 49152

__global__ __launch_bounds__(256, 2)
void qkv_mma_kernel(const float* __restrict__ x, const float* __restrict__ v1,
                    const float* __restrict__ Wk, const float* __restrict__ Wq,
                    const float* __restrict__ Wv,
                    const float* __restrict__ lamb_p,
                    float* __restrict__ v1dst)
{
    extern __shared__ char smem[];
    const unsigned sb = smem_u32(smem);
    const int tid  = threadIdx.x;
    const int warp = tid >> 5;
    const int lane = tid & 31;
    const int wm   = warp & 3;
    const int wn   = warp >> 2;
    const int mat  = blockIdx.x;       // 0:K 1:Q 2:V
    const int row0 = blockIdx.y * 128;
    const float* __restrict__ W = (mat == 0) ? Wk : (mat == 1) ? Wq : Wv;

    float4 pa[4][2];
    float4 pw[4];
    const int arow = tid >> 3;
    const int ac8  = tid & 7;

    auto load_a = [&](int k0) {
        #pragma unroll
        for (int it = 0; it < 4; it++) {
            int row = arow + it * 32;
            const float* p = &x[(size_t)(row0 + row) * C_ + k0 + ac8 * 8];
            pa[it][0] = *reinterpret_cast<const float4*>(p);
            pa[it][1] = *reinterpret_cast<const float4*>(p + 4);
        }
    };
    auto load_w = [&](int k0) {
        #pragma unroll
        for (int it = 0; it < 4; it++) {
            int idx = tid + it * 256;
            int k   = idx >> 4;
            int c4  = idx & 15;
            pw[it] = *reinterpret_cast<const float4*>(
                &W[(size_t)(k0 + k) * H_ + c4 * 4]);
        }
    };
    auto store_ab = [&](int buf) {
        #pragma unroll
        for (int it = 0; it < 4; it++) {
            int row = arow + it * 32;
            unsigned boff = row * 128 + ((ac8 * 16) ^ ((row & 7) << 4));
            *reinterpret_cast<uint4*>(smem + SA(buf) + boff) =
                round8(pa[it][0], pa[it][1]);
        }
        #pragma unroll
        for (int it = 0; it < 4; it++) {
            int idx = tid + it * 256;
            int k   = idx >> 4;
            int c4  = idx & 15;
            uint2 h;
            h.x = round2(pw[it].x, pw[it].y);
            h.y = round2(pw[it].z, pw[it].w);
            unsigned boff = k * 128 + ((c4 * 8) ^ ((k & 7) << 4));
            *reinterpret_cast<uint2*>(smem + SB(buf) + boff) = h;
        }
    };

    const int r   = lane & 7;
    const int sel = lane >> 3;
    const unsigned rx = r << 4;
    unsigned rowA[2], kselA = (sel >> 1) * 16;
    #pragma unroll
    for (int mt = 0; mt < 2; mt++)
        rowA[mt] = (wm * 32 + mt * 16 + r + (sel & 1) * 8) * 128;
    unsigned offT[2];
    #pragma unroll
    for (int v = 0; v < 2; v++)
        offT[v] = (((2 * (wn * 2 + v) + (sel >> 1)) * 16) ^ rx);
    const int rbT_lane = (sel & 1) * 8 + r;

    float acc[2][4][4];
    #pragma unroll
    for (int mt = 0; mt < 2; mt++)
        #pragma unroll
        for (int nt = 0; nt < 4; nt++)
            #pragma unroll
            for (int e = 0; e < 4; e++) acc[mt][nt][e] = 0.0f;

    load_a(0);
    load_w(0);
    store_ab(0);
    __syncthreads();

    for (int t = 0; t < QK_STAGES; t++) {
        const int cur = t & 1;
        if (t + 1 < QK_STAGES) {
            load_a((t + 1) * 64);
            load_w((t + 1) * 64);
        }

        const unsigned sa = sb + SA(cur);
        const unsigned sbh = sb + SB(cur);

        #pragma unroll
        for (int ks = 0; ks < 4; ks++) {
            const unsigned kb = ks * 32;
            unsigned aH[2][4], bT[2][4];
            #pragma unroll
            for (int mt = 0; mt < 2; mt++) {
                unsigned off = ((kb + kselA) ^ rx);
                ldsm4(aH[mt], sa + rowA[mt] + off);
            }
            {
                unsigned rb = (ks * 16 + rbT_lane) * 128;
                ldsm4_t(bT[0], sbh + rb + offT[0]);
                ldsm4_t(bT[1], sbh + rb + offT[1]);
            }
            #pragma unroll
            for (int mt = 0; mt < 2; mt++)
                #pragma unroll
                for (int nt = 0; nt < 4; nt++)
                    mma_f16(acc[mt][nt], aH[mt], &bT[nt >> 1][(nt & 1) * 2]);
        }
        if (t + 1 < QK_STAGES) store_ab((t + 1) & 1);
        __syncthreads();
    }

    const float lam = *lamb_p;
    const int qr = lane >> 2;
    const int qc = (lane & 3) * 2;
    #pragma unroll
    for (int mt = 0; mt < 2; mt++)
        #pragma unroll
        for (int nt = 0; nt < 4; nt++)
            #pragma unroll
            for (int half = 0; half < 2; half++) {
                int row = row0 + wm * 32 + mt * 16 + qr + half * 8;
                int col = wn * 32 + nt * 8 + qc;
                float vx = acc[mt][nt][half * 2];
                float vy = acc[mt][nt][half * 2 + 1];
                size_t off = (size_t)row * H_ + col;
                if (mat == 0) {
                    *reinterpret_cast<unsigned*>(&g_Kh[off]) = round2(vx, vy);
                } else if (mat == 1) {
                    *reinterpret_cast<unsigned*>(&g_Qh[off]) = round2(vx, vy);
                } else {
                    float2 vv = *reinterpret_cast<const float2*>(&v1[off]);
                    if (v1dst != nullptr)
                        *reinterpret_cast<float2*>(&v1dst[off]) = vv;
                    vx = (1.0f - lam) * vx + lam * vv.x;
                    vy = (1.0f - lam) * vy + lam * vv.y;
                    *reinterpret_cast<unsigned*>(&g_Vh[off]) = round2(vx, vy);
                }
            }
}

// ============================================================================
// Tensor-core flash attention — R14 structure, 128-key k-blocks.
// Half the barriers / softmax chains per key vs R14; occ 1 (reg budget 255).
// Persistent Q fragments; base-2 fp16x2 ex2 softmax; li via ones-column MMA.
// ============================================================================
#define AT_QO   34816
#define AT_KV(b) (AT_QO + (b)*32768)
#define AT_SMEM (AT_QO + 2*32768)
#define OTS 132

__global__ __launch_bounds__(256, 1)
void attn_tc_kernel(const float* __restrict__ Wproj,
                    const float* __restrict__ bproj,
                    float* __restrict__ out)
{
    extern __shared__ char smem[];
    const unsigned sb = smem_u32(smem);
    const int bid  = blockIdx.x;
    const int b    = bid & 15;
    const int qt   = 15 - (bid >> 4);        // heavy tiles first
    const int tid  = threadIdx.x;
    const int warp = tid >> 5;
    const int lane = tid & 31;
    const int r    = lane & 7;
    const int sel  = lane >> 3;
    const unsigned rx = r << 4;
    const int q0   = qt * 128;
    const int rowbase = b * T_;
    const int nkb  = qt + 1;                 // 128-key blocks

    unsigned b_ones[2];
    b_ones[0] = b_ones[1] = ((lane >> 2) == 0) ? 0x3C003C00u : 0u;

    // K/V tile: 128 keys x 64 d, Kh at +0, Vh at +16384 within buffer
    auto issue_kv = [&](int kb, int buf) {
        const __half* srcs[2] = {g_Kh, g_Vh};
        const unsigned dbase = sb + AT_KV(buf);
        #pragma unroll
        for (int it = 0; it < 8; it++) {
            int idx = tid + it * 256;          // 0..2047
            int arr = idx >> 10;
            int row = (idx >> 3) & 127;
            int c   = idx & 7;
            const void* src = &srcs[arr][(size_t)(rowbase + kb * 128 + row) * H_ + c * 8];
            unsigned dst = dbase + arr * 16384 + row * 128 + ((c * 16) ^ ((row & 7) << 4));
            cp_async16(dst, src);
        }
        cp_commit();
    };

    issue_kv(0, 0);

    #pragma unroll
    for (int it = 0; it < 4; it++) {
        int idx = tid + it * 256;              // 0..1023
        int row = (idx >> 3) & 127;
        int c   = idx & 7;
        uint4 v = *reinterpret_cast<const uint4*>(
            &g_Qh[(size_t)(rowbase + q0 + row) * H_ + c * 8]);
        *reinterpret_cast<uint4*>(
            smem + row * 128 + ((c * 16) ^ ((row & 7) << 4))) = v;
    }
    cp_wait<0>();
    __syncthreads();

    unsigned qh[4][4];
    {
        int rowA = warp * 16 + r + (sel & 1) * 8;
        unsigned rb = rowA * 128;
        #pragma unroll
        for (int ks = 0; ks < 4; ks++) {
            unsigned off = ((ks * 32 + (sel >> 1) * 16) ^ rx);
            ldsm4(qh[ks], sb + rb + off);
        }
    }

    float oacc[8][4];
    float lacc[4];
    #pragma unroll
    for (int j = 0; j < 8; j++)
        #pragma unroll
        for (int e = 0; e < 4; e++) oacc[j][e] = 0.0f;
    #pragma unroll
    for (int e = 0; e < 4; e++) lacc[e] = 0.0f;
    float mi[2] = {-1e30f, -1e30f};

    const float alpha = 0.18033688f;   // 0.125 * log2(e)
    const int rk = r + ((sel & 2) ? 8 : 0);

    for (int kb = 0; kb < nkb; kb++) {
        const unsigned kvb = sb + AT_KV(kb & 1);
        cp_wait<0>();
        __syncthreads();
        if (kb + 1 < nkb) issue_kv(kb + 1, (kb + 1) & 1);

        // ---- S = Q K^T over 128 keys (16 n8 tiles) ----
        float sacc[16][4];
        #pragma unroll
        for (int j = 0; j < 16; j++)
            #pragma unroll
            for (int e = 0; e < 4; e++) sacc[j][e] = 0.0f;

        #pragma unroll
        for (int ks = 0; ks < 4; ks++) {
            const unsigned koff = ((ks * 32 + (sel & 1) * 16) ^ rx);
            unsigned kh[8][4];
            #pragma unroll
            for (int u = 0; u < 8; u++)
                ldsm4(kh[u], kvb + (u * 16 + rk) * 128 + koff);
            #pragma unroll
            for (int u = 0; u < 8; u++)
                #pragma unroll
                for (int nn = 0; nn < 2; nn++)
                    mma_f16(sacc[u * 2 + nn], qh[ks], &kh[u][nn * 2]);
        }

        // ---- scale (base-2) + causal mask ----
        if (kb * 128 + 127 > q0 + warp * 16) {
            #pragma unroll
            for (int j = 0; j < 16; j++)
                #pragma unroll
                for (int e = 0; e < 4; e++) {
                    int key  = kb * 128 + j * 8 + (lane & 3) * 2 + (e & 1);
                    int qrow = q0 + warp * 16 + (lane >> 2) + (e >> 1) * 8;
                    float v = sacc[j][e] * alpha;
                    sacc[j][e] = (key <= qrow) ? v : -1e30f;
                }
        } else {
            #pragma unroll
            for (int j = 0; j < 16; j++)
                #pragma unroll
                for (int e = 0; e < 4; e++) sacc[j][e] *= alpha;
        }

        // ---- online softmax over 128 keys -> P fragments ----
        unsigned pfh[8][4];
        #pragma unroll
        for (int h = 0; h < 2; h++) {
            float mx = -1e30f;
            #pragma unroll
            for (int j = 0; j < 16; j++)
                mx = fmaxf(mx, fmaxf(sacc[j][h*2], sacc[j][h*2+1]));
            mx = fmaxf(mx, __shfl_xor_sync(0xffffffffu, mx, 1));
            mx = fmaxf(mx, __shfl_xor_sync(0xffffffffu, mx, 2));
            float mnew = fmaxf(mi[h], mx);
            float corr = exp2f(mi[h] - mnew);
            mi[h] = mnew;
            #pragma unroll
            for (int j = 0; j < 16; j++) {
                __half2 d2 = __floats2half2_rn(sacc[j][h*2]   - mnew,
                                               sacc[j][h*2+1] - mnew);
                pfh[j >> 1][(j & 1) * 2 + h] =
                    h2exp2(*reinterpret_cast<unsigned*>(&d2));
            }
            #pragma unroll
            for (int j = 0; j < 8; j++) {
                oacc[j][h*2]   *= corr;
                oacc[j][h*2+1] *= corr;
            }
            lacc[h*2]   *= corr;
            lacc[h*2+1] *= corr;
        }

        // ---- O += P V ; li via ones-column MMA ----
        #pragma unroll
        for (int kt = 0; kt < 8; kt++) {
            unsigned vh[4][4];
            const unsigned rb = (kt * 16 + (sel & 1) * 8 + r) * 128;
            #pragma unroll
            for (int u = 0; u < 4; u++) {
                unsigned off = (((2 * u + (sel >> 1)) * 16) ^ rx);
                ldsm4_t(vh[u], kvb + 16384 + rb + off);
            }
            #pragma unroll
            for (int u = 0; u < 4; u++)
                #pragma unroll
                for (int nn = 0; nn < 2; nn++)
                    mma_f16(oacc[u * 2 + nn], pfh[kt], &vh[u][nn * 2]);
            mma_f16(lacc, pfh[kt], b_ones);
        }
    }

    // ---- epilogue ----
    __syncthreads();
    float li0 = __shfl_sync(0xffffffffu, lacc[0], lane & 28);
    float li1 = __shfl_sync(0xffffffffu, lacc[2], lane & 28);
    float* Ot = reinterpret_cast<float*>(smem);
    {
        float inv0 = 1.0f / li0, inv1 = 1.0f / li1;
        #pragma unroll
        for (int j = 0; j < 8; j++)
            #pragma unroll
            for (int e = 0; e < 4; e++) {
                int qrel = warp * 16 + (lane >> 2) + (e >> 1) * 8;
                int d    = j * 8 + (lane & 3) * 2 + (e & 1);
                Ot[d * OTS + qrel] = oacc[j][e] * ((e >> 1) ? inv1 : inv0);
            }
    }
    __syncthreads();

    const int tx = tid & 15;
    const int ty = tid >> 4;
    float2 r2[8][2];
    #pragma unroll
    for (int i = 0; i < 8; i++) {
        r2[i][0] = make_float2(0.f, 0.f);
        r2[i][1] = make_float2(0.f, 0.f);
    }
    #pragma unroll 4
    for (int d = 0; d < 64; d++) {
        float4 a0 = *reinterpret_cast<const float4*>(&Ot[d * OTS + ty * 8]);
        float4 a1 = *reinterpret_cast<const float4*>(&Ot[d * OTS + ty * 8 + 4]);
        float4 w  = *reinterpret_cast<const float4*>(&Wproj[d * 64 + tx * 4]);
        float2 w01 = make_float2(w.x, w.y);
        float2 w23 = make_float2(w.z, w.w);
        float a[8] = {a0.x, a0.y, a0.z, a0.w, a1.x, a1.y, a1.z, a1.w};
        #pragma unroll
        for (int i = 0; i < 8; i++) {
            float2 ad = dup2(a[i]);
            r2[i][0] = ffma2(ad, w01, r2[i][0]);
            r2[i][1] = ffma2(ad, w23, r2[i][1]);
        }
    }
    float4 bb = *reinterpret_cast<const float4*>(&bproj[tx * 4]);
    const size_t baseo = (size_t)b * T_ * H_;
    #pragma unroll
    for (int i = 0; i < 8; i++) {
        float4 ov = make_float4(r2[i][0].x + bb.x, r2[i][0].y + bb.y,
                                r2[i][1].x + bb.z, r2[i][1].y + bb.w);
        *reinterpret_cast<float4*>(
            &out[baseo + (size_t)(q0 + ty * 8 + i) * H_ + tx * 4]) = ov;
    }
}

extern "C" void kernel_launch(void* const* d_in, const int* in_sizes, int n_in,
                              void* d_out, int out_size)
{
    const float* x     = (const float*)d_in[0];
    const float* v1    = (const float*)d_in[1];
    const float* Wk    = (const float*)d_in[2];
    const float* Wq    = (const float*)d_in[3];
    const float* Wv    = (const float*)d_in[4];
    const float* Wproj = (const float*)d_in[5];
    const float* bproj = (const float*)d_in[6];
    const float* lamb  = (const float*)d_in[7];
    float* out = (float*)d_out;

    cudaFuncSetAttribute(qkv_mma_kernel,
                         cudaFuncAttributeMaxDynamicSharedMemorySize, QM_SMEM);
    cudaFuncSetAttribute(attn_tc_kernel,
                         cudaFuncAttributeMaxDynamicSharedMemorySize, AT_SMEM);

    float* v1dst = (out_size >= 2 * BT_ * H_) ? (out + (size_t)BT_ * H_) : nullptr;
    qkv_mma_kernel<<<dim3(3, BT_ / 128), 256, QM_SMEM>>>(x, v1, Wk, Wq, Wv,
                                                         lamb, v1dst);
    attn_tc_kernel<<<16 * B_, 256, AT_SMEM>>>(Wproj, bproj, out);
}

// round 17
// speedup vs baseline: 1.0978x; 1.0045x over previous
#include <cuda_runtime.h>
#include <cuda_fp16.h>
#include <math.h>

#define B_  16
#define T_  2048
#define C_  768
#define H_  64
#define BT_ (B_*T_)

// Scratch (allocation-free rule: device globals) — all fp16-rounded
__device__ __half g_Qh[BT_*H_];
__device__ __half g_Kh[BT_*H_];
__device__ __half g_Vh[BT_*H_];

// ---------------------------------------------------------------------------
// helpers
// ---------------------------------------------------------------------------
__device__ __forceinline__ unsigned smem_u32(const void* p) {
    unsigned a;
    asm("{ .reg .u64 t; cvta.to.shared.u64 t, %1; cvt.u32.u64 %0, t; }"
        : "=r"(a) : "l"(p));
    return a;
}
__device__ __forceinline__ void ldsm4(unsigned* r, unsigned addr) {
    asm volatile("ldmatrix.sync.aligned.m8n8.x4.shared.b16 {%0,%1,%2,%3}, [%4];"
                 : "=r"(r[0]), "=r"(r[1]), "=r"(r[2]), "=r"(r[3]) : "r"(addr));
}
__device__ __forceinline__ void ldsm4_t(unsigned* r, unsigned addr) {
    asm volatile("ldmatrix.sync.aligned.m8n8.x4.trans.shared.b16 {%0,%1,%2,%3}, [%4];"
                 : "=r"(r[0]), "=r"(r[1]), "=r"(r[2]), "=r"(r[3]) : "r"(addr));
}
__device__ __forceinline__ void mma_f16(float* c, const unsigned* a, const unsigned* b) {
    asm volatile(
        "mma.sync.aligned.m16n8k16.row.col.f32.f16.f16.f32 "
        "{%0,%1,%2,%3}, {%4,%5,%6,%7}, {%8,%9}, {%0,%1,%2,%3};"
        : "+f"(c[0]), "+f"(c[1]), "+f"(c[2]), "+f"(c[3])
        : "r"(a[0]), "r"(a[1]), "r"(a[2]), "r"(a[3]), "r"(b[0]), "r"(b[1]));
}
__device__ __forceinline__ void cp_async16(unsigned dst, const void* src) {
    asm volatile("cp.async.cg.shared.global [%0], [%1], 16;"
                 :: "r"(dst), "l"(src) : "memory");
}
__device__ __forceinline__ void cp_commit() {
    asm volatile("cp.async.commit_group;" ::: "memory");
}
template<int N> __device__ __forceinline__ void cp_wait() {
    asm volatile("cp.async.wait_group %0;" :: "n"(N) : "memory");
}
// packed fp16x2 exp2
__device__ __forceinline__ unsigned h2exp2(unsigned d) {
    unsigned r;
    asm("ex2.approx.f16x2 %0, %1;" : "=r"(r) : "r"(d));
    return r;
}

union F2U { float2 f; unsigned long long u; };
__device__ __forceinline__ float2 ffma2(float2 a, float2 b, float2 c) {
    F2U A, Bv, C, D;
    A.f = a; Bv.f = b; C.f = c;
    asm("fma.rn.f32x2 %0, %1, %2, %3;"
        : "=l"(D.u) : "l"(A.u), "l"(Bv.u), "l"(C.u));
    return D.f;
}
__device__ __forceinline__ float2 dup2(float a) { return make_float2(a, a); }

// pack two fp32 into f16x2 (plain round)
__device__ __forceinline__ unsigned round2(float x, float y) {
    __half2 h2 = __halves2half2(__float2half_rn(x), __float2half_rn(y));
    return *reinterpret_cast<unsigned*>(&h2);
}
// pack 8 fp32 -> uint4 fp16
__device__ __forceinline__ uint4 round8(const float4& a, const float4& b) {
    uint4 o;
    o.x = round2(a.x, a.y);
    o.y = round2(a.z, a.w);
    o.z = round2(b.x, b.y);
    o.w = round2(b.z, b.w);
    return o;
}

// ============================================================================
// QKV GEMM on mma.sync fp16, 1-pass (unchanged from R14/R16).
// ============================================================================
#define QK_STAGES 12
#define SA(b) ((b)*24576)
#define SB(b) ((b)*24576 + 16384)
#define QM_SMEM 49152

__global__ __launch_bounds__(256, 2)
void qkv_mma_kernel(const float* __restrict__ x, const float* __restrict__ v1,
                    const float* __restrict__ Wk, const float* __restrict__ Wq,
                    const float* __restrict__ Wv,
                    const float* __restrict__ lamb_p,
                    float* __restrict__ v1dst)
{
    extern __shared__ char smem[];
    const unsigned sb = smem_u32(smem);
    const int tid  = threadIdx.x;
    const int warp = tid >> 5;
    const int lane = tid & 31;
    const int wm   = warp & 3;
    const int wn   = warp >> 2;
    const int mat  = blockIdx.x;       // 0:K 1:Q 2:V
    const int row0 = blockIdx.y * 128;
    const float* __restrict__ W = (mat == 0) ? Wk : (mat == 1) ? Wq : Wv;

    float4 pa[4][2];
    float4 pw[4];
    const int arow = tid >> 3;
    const int ac8  = tid & 7;

    auto load_a = [&](int k0) {
        #pragma unroll
        for (int it = 0; it < 4; it++) {
            int row = arow + it * 32;
            const float* p = &x[(size_t)(row0 + row) * C_ + k0 + ac8 * 8];
            pa[it][0] = *reinterpret_cast<const float4*>(p);
            pa[it][1] = *reinterpret_cast<const float4*>(p + 4);
        }
    };
    auto load_w = [&](int k0) {
        #pragma unroll
        for (int it = 0; it < 4; it++) {
            int idx = tid + it * 256;
            int k   = idx >> 4;
            int c4  = idx & 15;
            pw[it] = *reinterpret_cast<const float4*>(
                &W[(size_t)(k0 + k) * H_ + c4 * 4]);
        }
    };
    auto store_ab = [&](int buf) {
        #pragma unroll
        for (int it = 0; it < 4; it++) {
            int row = arow + it * 32;
            unsigned boff = row * 128 + ((ac8 * 16) ^ ((row & 7) << 4));
            *reinterpret_cast<uint4*>(smem + SA(buf) + boff) =
                round8(pa[it][0], pa[it][1]);
        }
        #pragma unroll
        for (int it = 0; it < 4; it++) {
            int idx = tid + it * 256;
            int k   = idx >> 4;
            int c4  = idx & 15;
            uint2 h;
            h.x = round2(pw[it].x, pw[it].y);
            h.y = round2(pw[it].z, pw[it].w);
            unsigned boff = k * 128 + ((c4 * 8) ^ ((k & 7) << 4));
            *reinterpret_cast<uint2*>(smem + SB(buf) + boff) = h;
        }
    };

    const int r   = lane & 7;
    const int sel = lane >> 3;
    const unsigned rx = r << 4;
    unsigned rowA[2], kselA = (sel >> 1) * 16;
    #pragma unroll
    for (int mt = 0; mt < 2; mt++)
        rowA[mt] = (wm * 32 + mt * 16 + r + (sel & 1) * 8) * 128;
    unsigned offT[2];
    #pragma unroll
    for (int v = 0; v < 2; v++)
        offT[v] = (((2 * (wn * 2 + v) + (sel >> 1)) * 16) ^ rx);
    const int rbT_lane = (sel & 1) * 8 + r;

    float acc[2][4][4];
    #pragma unroll
    for (int mt = 0; mt < 2; mt++)
        #pragma unroll
        for (int nt = 0; nt < 4; nt++)
            #pragma unroll
            for (int e = 0; e < 4; e++) acc[mt][nt][e] = 0.0f;

    load_a(0);
    load_w(0);
    store_ab(0);
    __syncthreads();

    for (int t = 0; t < QK_STAGES; t++) {
        const int cur = t & 1;
        if (t + 1 < QK_STAGES) {
            load_a((t + 1) * 64);
            load_w((t + 1) * 64);
        }

        const unsigned sa = sb + SA(cur);
        const unsigned sbh = sb + SB(cur);

        #pragma unroll
        for (int ks = 0; ks < 4; ks++) {
            const unsigned kb = ks * 32;
            unsigned aH[2][4], bT[2][4];
            #pragma unroll
            for (int mt = 0; mt < 2; mt++) {
                unsigned off = ((kb + kselA) ^ rx);
                ldsm4(aH[mt], sa + rowA[mt] + off);
            }
            {
                unsigned rb = (ks * 16 + rbT_lane) * 128;
                ldsm4_t(bT[0], sbh + rb + offT[0]);
                ldsm4_t(bT[1], sbh + rb + offT[1]);
            }
            #pragma unroll
            for (int mt = 0; mt < 2; mt++)
                #pragma unroll
                for (int nt = 0; nt < 4; nt++)
                    mma_f16(acc[mt][nt], aH[mt], &bT[nt >> 1][(nt & 1) * 2]);
        }
        if (t + 1 < QK_STAGES) store_ab((t + 1) & 1);
        __syncthreads();
    }

    const float lam = *lamb_p;
    const int qr = lane >> 2;
    const int qc = (lane & 3) * 2;
    #pragma unroll
    for (int mt = 0; mt < 2; mt++)
        #pragma unroll
        for (int nt = 0; nt < 4; nt++)
            #pragma unroll
            for (int half = 0; half < 2; half++) {
                int row = row0 + wm * 32 + mt * 16 + qr + half * 8;
                int col = wn * 32 + nt * 8 + qc;
                float vx = acc[mt][nt][half * 2];
                float vy = acc[mt][nt][half * 2 + 1];
                size_t off = (size_t)row * H_ + col;
                if (mat == 0) {
                    *reinterpret_cast<unsigned*>(&g_Kh[off]) = round2(vx, vy);
                } else if (mat == 1) {
                    *reinterpret_cast<unsigned*>(&g_Qh[off]) = round2(vx, vy);
                } else {
                    float2 vv = *reinterpret_cast<const float2*>(&v1[off]);
                    if (v1dst != nullptr)
                        *reinterpret_cast<float2*>(&v1dst[off]) = vv;
                    vx = (1.0f - lam) * vx + lam * vv.x;
                    vy = (1.0f - lam) * vy + lam * vv.y;
                    *reinterpret_cast<unsigned*>(&g_Vh[off]) = round2(vx, vy);
                }
            }
}

// ============================================================================
// Tensor-core flash attention — persistent CTAs, serpentine LPT schedule.
// Grid = 148 (one CTA/SM); CTA w handles tile w, then tile 295-w (if valid).
// Tile idx -> qt = 15-(idx>>4) (heavy first), b = idx&15.
// Body per tile = R16: 128-key blocks, base-2 fp16x2 ex2, li via ones-MMA.
// ============================================================================
#define AT_QO   34816
#define AT_KV(b) (AT_QO + (b)*32768)
#define AT_SMEM (AT_QO + 2*32768)
#define OTS 132
#define AT_GRID 148

__global__ __launch_bounds__(256, 1)
void attn_tc_kernel(const float* __restrict__ Wproj,
                    const float* __restrict__ bproj,
                    float* __restrict__ out)
{
    extern __shared__ char smem[];
    const unsigned sb = smem_u32(smem);
    const int tid  = threadIdx.x;
    const int warp = tid >> 5;
    const int lane = tid & 31;
    const int r    = lane & 7;
    const int sel  = lane >> 3;
    const unsigned rx = r << 4;
    const int tx = tid & 15;
    const int ty = tid >> 4;

    unsigned b_ones[2];
    b_ones[0] = b_ones[1] = ((lane >> 2) == 0) ? 0x3C003C00u : 0u;

    const float alpha = 0.18033688f;   // 0.125 * log2(e)
    const int rk = r + ((sel & 2) ? 8 : 0);
    const unsigned rbQ = (warp * 16 + r + (sel & 1) * 8) * 128;
    const unsigned kselQ = (sel >> 1) * 16;

    #pragma unroll 1
    for (int rnd = 0; rnd < 2; rnd++) {
        int idx = (rnd == 0) ? (int)blockIdx.x : (295 - (int)blockIdx.x);
        if (rnd == 1 && (idx < AT_GRID || idx > 255)) break;

        const int qt = 15 - (idx >> 4);
        const int b  = idx & 15;
        const int q0 = qt * 128;
        const int rowbase = b * T_;
        const int nkb = qt + 1;
        const size_t baseo = (size_t)b * T_ * H_;

        auto issue_kv = [&](int kb, int buf) {
            const __half* srcs[2] = {g_Kh, g_Vh};
            const unsigned dbase = sb + AT_KV(buf);
            #pragma unroll
            for (int it = 0; it < 8; it++) {
                int i2 = tid + it * 256;
                int arr = i2 >> 10;
                int row = (i2 >> 3) & 127;
                int c   = i2 & 7;
                const void* src = &srcs[arr][(size_t)(rowbase + kb * 128 + row) * H_ + c * 8];
                unsigned dst = dbase + arr * 16384 + row * 128 + ((c * 16) ^ ((row & 7) << 4));
                cp_async16(dst, src);
            }
            cp_commit();
        };

        issue_kv(0, 0);

        // stage Q tile
        #pragma unroll
        for (int it = 0; it < 4; it++) {
            int i2 = tid + it * 256;
            int row = (i2 >> 3) & 127;
            int c   = i2 & 7;
            uint4 v = *reinterpret_cast<const uint4*>(
                &g_Qh[(size_t)(rowbase + q0 + row) * H_ + c * 8]);
            *reinterpret_cast<uint4*>(
                smem + row * 128 + ((c * 16) ^ ((row & 7) << 4))) = v;
        }
        cp_wait<0>();
        __syncthreads();

        unsigned qh[4][4];
        #pragma unroll
        for (int ks = 0; ks < 4; ks++)
            ldsm4(qh[ks], sb + rbQ + ((ks * 32 + kselQ) ^ rx));

        float oacc[8][4];
        float lacc[4];
        #pragma unroll
        for (int j = 0; j < 8; j++)
            #pragma unroll
            for (int e = 0; e < 4; e++) oacc[j][e] = 0.0f;
        #pragma unroll
        for (int e = 0; e < 4; e++) lacc[e] = 0.0f;
        float mi[2] = {-1e30f, -1e30f};

        for (int kb = 0; kb < nkb; kb++) {
            const unsigned kvb = sb + AT_KV(kb & 1);
            cp_wait<0>();
            __syncthreads();
            if (kb + 1 < nkb) issue_kv(kb + 1, (kb + 1) & 1);

            float sacc[16][4];
            #pragma unroll
            for (int j = 0; j < 16; j++)
                #pragma unroll
                for (int e = 0; e < 4; e++) sacc[j][e] = 0.0f;

            #pragma unroll
            for (int ks = 0; ks < 4; ks++) {
                const unsigned koff = ((ks * 32 + (sel & 1) * 16) ^ rx);
                unsigned kh[8][4];
                #pragma unroll
                for (int u = 0; u < 8; u++)
                    ldsm4(kh[u], kvb + (u * 16 + rk) * 128 + koff);
                #pragma unroll
                for (int u = 0; u < 8; u++)
                    #pragma unroll
                    for (int nn = 0; nn < 2; nn++)
                        mma_f16(sacc[u * 2 + nn], qh[ks], &kh[u][nn * 2]);
            }

            if (kb * 128 + 127 > q0 + warp * 16) {
                #pragma unroll
                for (int j = 0; j < 16; j++)
                    #pragma unroll
                    for (int e = 0; e < 4; e++) {
                        int key  = kb * 128 + j * 8 + (lane & 3) * 2 + (e & 1);
                        int qrow = q0 + warp * 16 + (lane >> 2) + (e >> 1) * 8;
                        float v = sacc[j][e] * alpha;
                        sacc[j][e] = (key <= qrow) ? v : -1e30f;
                    }
            } else {
                #pragma unroll
                for (int j = 0; j < 16; j++)
                    #pragma unroll
                    for (int e = 0; e < 4; e++) sacc[j][e] *= alpha;
            }

            unsigned pfh[8][4];
            #pragma unroll
            for (int h = 0; h < 2; h++) {
                float mx = -1e30f;
                #pragma unroll
                for (int j = 0; j < 16; j++)
                    mx = fmaxf(mx, fmaxf(sacc[j][h*2], sacc[j][h*2+1]));
                mx = fmaxf(mx, __shfl_xor_sync(0xffffffffu, mx, 1));
                mx = fmaxf(mx, __shfl_xor_sync(0xffffffffu, mx, 2));
                float mnew = fmaxf(mi[h], mx);
                float corr = exp2f(mi[h] - mnew);
                mi[h] = mnew;
                #pragma unroll
                for (int j = 0; j < 16; j++) {
                    __half2 d2 = __floats2half2_rn(sacc[j][h*2]   - mnew,
                                                   sacc[j][h*2+1] - mnew);
                    pfh[j >> 1][(j & 1) * 2 + h] =
                        h2exp2(*reinterpret_cast<unsigned*>(&d2));
                }
                #pragma unroll
                for (int j = 0; j < 8; j++) {
                    oacc[j][h*2]   *= corr;
                    oacc[j][h*2+1] *= corr;
                }
                lacc[h*2]   *= corr;
                lacc[h*2+1] *= corr;
            }

            #pragma unroll
            for (int kt = 0; kt < 8; kt++) {
                unsigned vh[4][4];
                const unsigned rb = (kt * 16 + (sel & 1) * 8 + r) * 128;
                #pragma unroll
                for (int u = 0; u < 4; u++) {
                    unsigned off = (((2 * u + (sel >> 1)) * 16) ^ rx);
                    ldsm4_t(vh[u], kvb + 16384 + rb + off);
                }
                #pragma unroll
                for (int u = 0; u < 4; u++)
                    #pragma unroll
                    for (int nn = 0; nn < 2; nn++)
                        mma_f16(oacc[u * 2 + nn], pfh[kt], &vh[u][nn * 2]);
                mma_f16(lacc, pfh[kt], b_ones);
            }
        }

        // ---- epilogue ----
        __syncthreads();
        float li0 = __shfl_sync(0xffffffffu, lacc[0], lane & 28);
        float li1 = __shfl_sync(0xffffffffu, lacc[2], lane & 28);
        float* Ot = reinterpret_cast<float*>(smem);
        {
            float inv0 = 1.0f / li0, inv1 = 1.0f / li1;
            #pragma unroll
            for (int j = 0; j < 8; j++)
                #pragma unroll
                for (int e = 0; e < 4; e++) {
                    int qrel = warp * 16 + (lane >> 2) + (e >> 1) * 8;
                    int d    = j * 8 + (lane & 3) * 2 + (e & 1);
                    Ot[d * OTS + qrel] = oacc[j][e] * ((e >> 1) ? inv1 : inv0);
                }
        }
        __syncthreads();

        float2 r2[8][2];
        #pragma unroll
        for (int i = 0; i < 8; i++) {
            r2[i][0] = make_float2(0.f, 0.f);
            r2[i][1] = make_float2(0.f, 0.f);
        }
        #pragma unroll 4
        for (int d = 0; d < 64; d++) {
            float4 a0 = *reinterpret_cast<const float4*>(&Ot[d * OTS + ty * 8]);
            float4 a1 = *reinterpret_cast<const float4*>(&Ot[d * OTS + ty * 8 + 4]);
            float4 w  = *reinterpret_cast<const float4*>(&Wproj[d * 64 + tx * 4]);
            float2 w01 = make_float2(w.x, w.y);
            float2 w23 = make_float2(w.z, w.w);
            float a[8] = {a0.x, a0.y, a0.z, a0.w, a1.x, a1.y, a1.z, a1.w};
            #pragma unroll
            for (int i = 0; i < 8; i++) {
                float2 ad = dup2(a[i]);
                r2[i][0] = ffma2(ad, w01, r2[i][0]);
                r2[i][1] = ffma2(ad, w23, r2[i][1]);
            }
        }
        float4 bb = *reinterpret_cast<const float4*>(&bproj[tx * 4]);
        #pragma unroll
        for (int i = 0; i < 8; i++) {
            float4 ov = make_float4(r2[i][0].x + bb.x, r2[i][0].y + bb.y,
                                    r2[i][1].x + bb.z, r2[i][1].y + bb.w);
            *reinterpret_cast<float4*>(
                &out[baseo + (size_t)(q0 + ty * 8 + i) * H_ + tx * 4]) = ov;
        }
        __syncthreads();   // Ot reads done before next tile re-stages Q
    }
}

extern "C" void kernel_launch(void* const* d_in, const int* in_sizes, int n_in,
                              void* d_out, int out_size)
{
    const float* x     = (const float*)d_in[0];
    const float* v1    = (const float*)d_in[1];
    const float* Wk    = (const float*)d_in[2];
    const float* Wq    = (const float*)d_in[3];
    const float* Wv    = (const float*)d_in[4];
    const float* Wproj = (const float*)d_in[5];
    const float* bproj = (const float*)d_in[6];
    const float* lamb  = (const float*)d_in[7];
    float* out = (float*)d_out;

    cudaFuncSetAttribute(qkv_mma_kernel,
                         cudaFuncAttributeMaxDynamicSharedMemorySize, QM_SMEM);
    cudaFuncSetAttribute(attn_tc_kernel,
                         cudaFuncAttributeMaxDynamicSharedMemorySize, AT_SMEM);

    float* v1dst = (out_size >= 2 * BT_ * H_) ? (out + (size_t)BT_ * H_) : nullptr;
    qkv_mma_kernel<<<dim3(3, BT_ / 128), 256, QM_SMEM>>>(x, v1, Wk, Wq, Wv,
                                                         lamb, v1dst);
    attn_tc_kernel<<<AT_GRID, 256, AT_SMEM>>>(Wproj, bproj, out);
}